// round 1
// baseline (speedup 1.0000x reference)
#include <cuda_runtime.h>

#define B_ 16
#define T_ 4096
#define D_ 512
#define R_ 256

#define BT 64
#define BK 16
#define NT (D_ / BK)   // 32 k-tiles

// Scratch (no allocations allowed)
__device__ float g_rnorm[B_ * T_];              // 256 KB
__device__ float g_K[B_ * R_ * D_];             // 8 MB: normalized landmark rows
__device__ int   g_lm[R_];

// ---------------------------------------------------------------------------
// Kernel A: reciprocal norms, one warp per row
// ---------------------------------------------------------------------------
__global__ void norm_kernel(const float* __restrict__ z) {
    int gwarp = (blockIdx.x * blockDim.x + threadIdx.x) >> 5;
    int lane  = threadIdx.x & 31;
    if (gwarp >= B_ * T_) return;
    const float4* row = (const float4*)(z + (size_t)gwarp * D_);
    float ss = 0.f;
#pragma unroll
    for (int i = 0; i < 4; i++) {
        float4 v = row[lane + 32 * i];
        ss += v.x * v.x + v.y * v.y + v.z * v.z + v.w * v.w;
    }
#pragma unroll
    for (int o = 16; o; o >>= 1) ss += __shfl_xor_sync(0xFFFFFFFFu, ss, o);
    if (lane == 0) g_rnorm[gwarp] = 1.0f / fmaxf(sqrtf(ss), 1e-12f);
}

// ---------------------------------------------------------------------------
// Kernel B: gather normalized K rows + landmark indices
// grid (R_, B_), 128 threads
// ---------------------------------------------------------------------------
__global__ void gather_kernel(const float* __restrict__ z) {
    int r = blockIdx.x, b = blockIdx.y;
    const double step = 4095.0 / 255.0;              // matches np.linspace
    int lm = (r == R_ - 1) ? (T_ - 1) : (int)((double)r * step);
    if (b == 0 && threadIdx.x == 0) g_lm[r] = lm;
    float rn = g_rnorm[b * T_ + lm];
    const float4* src = (const float4*)(z + ((size_t)b * T_ + lm) * D_);
    float4* dst = (float4*)(g_K + ((size_t)b * R_ + r) * D_);
    float4 v = src[threadIdx.x];
    v.x *= rn; v.y *= rn; v.z *= rn; v.w *= rn;
    dst[threadIdx.x] = v;
}

// ---------------------------------------------------------------------------
// Kernel C: fused GEMM (64 rows x 256 cols per CTA) + epilogue
// threads: 256 = 8 warps; warp = row-group (8 rows), lane = col-group (8 cols)
// ---------------------------------------------------------------------------
__global__ __launch_bounds__(256, 2)
void main_kernel(const float* __restrict__ z,
                 const float* __restrict__ gw,
                 const float* __restrict__ ta,
                 float* __restrict__ out) {
    __shared__ float As[BK][BT + 4];   // padded: float4-aligned, fewer STS conflicts
    __shared__ float Bs[BK][R_];
    __shared__ float s_rn[BT];
    __shared__ int   s_lm[R_];

    const int tid  = threadIdx.x;
    const int lane = tid & 31;
    const int warp = tid >> 5;
    const int b    = blockIdx.y;
    const int t0   = blockIdx.x * BT;

    if (tid < BT) s_rn[tid] = g_rnorm[b * T_ + t0 + tid];
    s_lm[tid] = g_lm[tid];             // 256 threads, 256 entries

    // --- global load indexing ---
    const int arow = tid >> 2;               // 0..63
    const int akc  = (tid & 3) * 4;          // 0,4,8,12
    const float4* gA = (const float4*)z +
        (((size_t)(b * T_ + t0 + arow) * D_ + akc) >> 2);   // + kt*4 per stage
    const float4* gB = (const float4*)g_K +
        (((size_t)(b * R_ + tid) * D_) >> 2);               // + kt*4 per stage

    float4 av, bv0, bv1, bv2, bv3;

    // prefetch stage 0
    av  = gA[0];
    bv0 = gB[0]; bv1 = gB[1]; bv2 = gB[2]; bv3 = gB[3];

    float acc[8][8];
#pragma unroll
    for (int i = 0; i < 8; i++)
#pragma unroll
        for (int j = 0; j < 8; j++) acc[i][j] = 0.f;

    __syncthreads();   // s_rn / s_lm ready

    for (int kt = 0; kt < NT; kt++) {
        // store prefetched tile to smem
        {
            float rn = s_rn[arow];
            As[akc + 0][arow] = av.x * rn;
            As[akc + 1][arow] = av.y * rn;
            As[akc + 2][arow] = av.z * rn;
            As[akc + 3][arow] = av.w * rn;
            Bs[ 0][tid] = bv0.x; Bs[ 1][tid] = bv0.y; Bs[ 2][tid] = bv0.z; Bs[ 3][tid] = bv0.w;
            Bs[ 4][tid] = bv1.x; Bs[ 5][tid] = bv1.y; Bs[ 6][tid] = bv1.z; Bs[ 7][tid] = bv1.w;
            Bs[ 8][tid] = bv2.x; Bs[ 9][tid] = bv2.y; Bs[10][tid] = bv2.z; Bs[11][tid] = bv2.w;
            Bs[12][tid] = bv3.x; Bs[13][tid] = bv3.y; Bs[14][tid] = bv3.z; Bs[15][tid] = bv3.w;
        }
        __syncthreads();

        // prefetch next stage (overlaps with compute below)
        if (kt + 1 < NT) {
            const float4* pa = gA + (kt + 1) * 4;
            const float4* pb = gB + (kt + 1) * 4;
            av  = pa[0];
            bv0 = pb[0]; bv1 = pb[1]; bv2 = pb[2]; bv3 = pb[3];
        }

        // compute on current tile
#pragma unroll
        for (int k = 0; k < BK; k++) {
            float4 a0 = *(const float4*)&As[k][warp * 8];
            float4 a1 = *(const float4*)&As[k][warp * 8 + 4];
            float4 b0 = *(const float4*)&Bs[k][lane * 8];
            float4 b1 = *(const float4*)&Bs[k][lane * 8 + 4];
            float a[8] = {a0.x, a0.y, a0.z, a0.w, a1.x, a1.y, a1.z, a1.w};
            float bb[8] = {b0.x, b0.y, b0.z, b0.w, b1.x, b1.y, b1.z, b1.w};
#pragma unroll
            for (int i = 0; i < 8; i++)
#pragma unroll
                for (int j = 0; j < 8; j++)
                    acc[i][j] = fmaf(a[i], bb[j], acc[i][j]);
        }
        __syncthreads();
    }

    // ---------------- epilogue ----------------
    float w0 = gw[0], w1 = gw[1], w2 = gw[2];
    float mx = fmaxf(w0, fmaxf(w1, w2));
    float e0 = __expf(w0 - mx), e1 = __expf(w1 - mx), e2 = __expf(w2 - mx);
    float esum = 1.0f / (e0 + e1 + e2);
    float a0c = e0 * esum, a1c = e1 * esum, a2c = e2 * esum;
    float tav  = ta[0];
    float a_td = fmaxf(tav, 0.f) + log1pf(__expf(-fabsf(tav)));   // softplus

    int lms[8];
#pragma unroll
    for (int j = 0; j < 8; j++) lms[j] = s_lm[lane * 8 + j];

#pragma unroll
    for (int i = 0; i < 8; i++) {
        int t = t0 + warp * 8 + i;
        float phi[8];
        float psum = 0.f;
#pragma unroll
        for (int j = 0; j < 8; j++) {
            float C  = acc[i][j];
            float c2 = C * C;
            float p = a0c * (0.5f * (1.f + C))
                    + a1c * (0.5f * (3.f * c2 - 1.f))
                    + a2c * (0.5f * (5.f * c2 * C - 3.f * C));
            int lmv = lms[j];
            float td = (float)(t - lmv) * (1.0f / 4096.0f);
            p = (lmv < t) ? p * __expf(-a_td * td) : 0.f;
            phi[j] = p;
            psum += p;
        }
#pragma unroll
        for (int o = 16; o; o >>= 1) psum += __shfl_xor_sync(0xFFFFFFFFu, psum, o);
        float rs = 1.0f / fmaxf(psum, 1e-6f);
        float* orow = out + (size_t)(b * T_ + t) * (R_ + 1);
#pragma unroll
        for (int j = 0; j < 8; j++) orow[lane * 8 + j] = phi[j] * rs;
        if (lane == 0) orow[R_] = 1.0f;
    }
}

// ---------------------------------------------------------------------------
extern "C" void kernel_launch(void* const* d_in, const int* in_sizes, int n_in,
                              void* d_out, int out_size) {
    const float* z  = (const float*)d_in[0];
    const float* gw = (const float*)d_in[1];
    const float* ta = (const float*)d_in[2];
    float* out = (float*)d_out;

    // A: 16*4096 rows, 1 warp/row, 8 warps/block
    norm_kernel<<<(B_ * T_) / 8, 256>>>(z);
    // B: gather K
    gather_kernel<<<dim3(R_, B_), 128>>>(z);
    // C: fused GEMM + epilogue
    main_kernel<<<dim3(T_ / BT, B_), 256>>>(z, gw, ta, out);
}

// round 14
// speedup vs baseline: 2.7635x; 2.7635x over previous
#include <cuda_runtime.h>
#include <cstdint>

#define B_ 16
#define T_ 4096
#define D_ 512
#define R_ 256
#define MT 128          // CTA M tile
#define BK 32           // k chunk
#define NCH (D_/BK)     // 16
#define NTH 512
#define PAD 36          // floats per smem row (bank-conflict-free, 16B-aligned)

// smem layout in floats
#define A_OFF(s)  ((s)*(MT*PAD + R_*PAD))
#define B_OFF(s)  (A_OFF(s) + MT*PAD)
#define TILES_SZ  (2*(MT*PAD + R_*PAD))
#define RN_OFF    TILES_SZ
#define LM_OFF    (TILES_SZ+128)
#define F_OFF     (TILES_SZ+384)
#define PART_OFF  (TILES_SZ+640)
#define SMEM_BYTES ((TILES_SZ+1152)*4)

__device__ float g_K[B_*R_*D_];      // normalized landmark rows, tf32-rounded
__device__ float g_rnorm[B_*T_];

// ---------------- helpers ----------------
static __device__ __forceinline__ uint32_t smem_u32(const void* p) {
    uint32_t a;
    asm("{ .reg .u64 t; cvta.to.shared.u64 t, %1; cvt.u32.u64 %0, t; }" : "=r"(a) : "l"(p));
    return a;
}
static __device__ __forceinline__ void cp16(uint32_t dst, const float* src) {
    asm volatile("cp.async.cg.shared.global [%0], [%1], 16;" :: "r"(dst), "l"(src));
}
#define CP_COMMIT() asm volatile("cp.async.commit_group;" ::: "memory")
#define CP_WAIT(n)  asm volatile("cp.async.wait_group %0;" :: "n"(n) : "memory")

static __device__ __forceinline__ uint32_t to_tf32(float f) {
    uint32_t u;
    asm("cvt.rna.tf32.f32 %0, %1;" : "=r"(u) : "f"(f));
    return u;
}
static __device__ __forceinline__ void mma_tf32(float* d, const uint32_t* a, const uint32_t* b) {
    asm volatile("mma.sync.aligned.m16n8k8.row.col.f32.tf32.tf32.f32 "
        "{%0,%1,%2,%3}, {%4,%5,%6,%7}, {%8,%9}, {%0,%1,%2,%3};"
        : "+f"(d[0]), "+f"(d[1]), "+f"(d[2]), "+f"(d[3])
        : "r"(a[0]), "r"(a[1]), "r"(a[2]), "r"(a[3]), "r"(b[0]), "r"(b[1]));
}

// ---------------------------------------------------------------------------
// Kernel A: reciprocal norms, one warp per row  (R1, measured 74% DRAM)
// ---------------------------------------------------------------------------
__global__ void norm_kernel(const float* __restrict__ z) {
    int gwarp = (blockIdx.x * blockDim.x + threadIdx.x) >> 5;
    int lane  = threadIdx.x & 31;
    if (gwarp >= B_ * T_) return;
    const float4* row = (const float4*)(z + (size_t)gwarp * D_);
    float ss = 0.f;
#pragma unroll
    for (int i = 0; i < 4; i++) {
        float4 v = row[lane + 32 * i];
        ss += v.x * v.x + v.y * v.y + v.z * v.z + v.w * v.w;
    }
#pragma unroll
    for (int o = 16; o; o >>= 1) ss += __shfl_xor_sync(0xFFFFFFFFu, ss, o);
    if (lane == 0) g_rnorm[gwarp] = 1.0f / fmaxf(sqrtf(ss), 1e-12f);
}

// ---------------------------------------------------------------------------
// Kernel B: gather normalized landmark rows, tf32-rounded.  grid (R_, B_), 128 thr
// ---------------------------------------------------------------------------
__global__ void gather_kernel(const float* __restrict__ z) {
    __shared__ float ws[4];
    int r = blockIdx.x, b = blockIdx.y, tid = threadIdx.x;
    int lm = (r == R_ - 1) ? (T_ - 1) : (int)((double)r * (4095.0 / 255.0));
    const float4* src = (const float4*)(z + ((size_t)b * T_ + lm) * D_);
    float4 v = src[tid];
    float ss = v.x*v.x + v.y*v.y + v.z*v.z + v.w*v.w;
#pragma unroll
    for (int o = 16; o; o >>= 1) ss += __shfl_xor_sync(0xFFFFFFFFu, ss, o);
    if ((tid & 31) == 0) ws[tid >> 5] = ss;
    __syncthreads();
    float rn = 1.0f / fmaxf(sqrtf(ws[0] + ws[1] + ws[2] + ws[3]), 1e-12f);
    size_t base = ((size_t)b * R_ + r) * D_ + tid * 4;
    float q[4] = {v.x*rn, v.y*rn, v.z*rn, v.w*rn};
#pragma unroll
    for (int i = 0; i < 4; i++)
        g_K[base + i] = __uint_as_float(to_tf32(q[i]));
}

// ---------------------------------------------------------------------------
// Main kernel: cp.async pipeline + mma.sync TF32 GEMM (128x256x512) + epilogue
// 512 threads = 16 warps; warp (wm = wid&3, wn = wid>>2) owns a 32x64 tile
// ---------------------------------------------------------------------------
__global__ __launch_bounds__(NTH, 1)
void main_kernel(const float* __restrict__ z,
                 const float* __restrict__ gw,
                 const float* __restrict__ ta,
                 float* __restrict__ out) {
    extern __shared__ float smemf[];
    const uint32_t sb = smem_u32(smemf);
    const int tid = threadIdx.x, wid = tid >> 5, lane = tid & 31;
    const int wm = wid & 3, wn = wid >> 2;
    const int g = lane >> 2, q = lane & 3;
    const int b = blockIdx.y, t0 = blockIdx.x * MT;
    const int bT = b * T_;

    float tav = ta[0];
    float a_td = fmaxf(tav, 0.f) + log1pf(__expf(-fabsf(tav)));   // softplus

    // landmark / decay tables + rnorms for this row block
    if (tid < R_) {
        int lm = (tid == R_ - 1) ? (T_ - 1) : (int)((double)tid * (4095.0 / 255.0));
        ((int*)(smemf + LM_OFF))[tid] = lm;
        smemf[F_OFF + tid] = __expf(a_td * (float)lm * (1.0f / 4096.0f));
    }
    if (tid < MT) smemf[RN_OFF + tid] = g_rnorm[bT + t0 + tid];

    // cp.async source bases (advance by BK floats per chunk)
    const float* zA = z + (size_t)(bT + t0) * D_;
    const float* gK = g_K + (size_t)b * R_ * D_;
    const int rA = tid >> 3, oA = tid & 7;    // A: 2 segs (rows rA, rA+64)
    const int rB = tid >> 3, oB = tid & 7;    // B: 4 segs (rows rB+0/64/128/192)

#define ISSUE(s, kc) do { \
    _Pragma("unroll") for (int i = 0; i < 2; i++) { \
        int row = rA + i * 64; \
        cp16(sb + (uint32_t)(A_OFF(s) + row*PAD + oA*4)*4, \
             zA + (size_t)row*D_ + (kc)*BK + oA*4); } \
    _Pragma("unroll") for (int i = 0; i < 4; i++) { \
        int row = rB + i * 64; \
        cp16(sb + (uint32_t)(B_OFF(s) + row*PAD + oB*4)*4, \
             gK + (size_t)row*D_ + (kc)*BK + oB*4); } \
    CP_COMMIT(); } while (0)

    float acc[2][8][4];
#pragma unroll
    for (int mi = 0; mi < 2; mi++)
#pragma unroll
        for (int nt = 0; nt < 8; nt++)
#pragma unroll
            for (int e = 0; e < 4; e++) acc[mi][nt][e] = 0.f;

#define COMPUTE(s) do { \
    const float* As = smemf + A_OFF(s); \
    const uint32_t* Bs = (const uint32_t*)(smemf + B_OFF(s)); \
    _Pragma("unroll") for (int kk = 0; kk < 4; kk++) { \
        const int kb = kk * 8; \
        uint32_t aa[2][4], bb[8][2]; \
        _Pragma("unroll") for (int mi = 0; mi < 2; mi++) { \
            int r0 = wm*32 + mi*16 + g; \
            aa[mi][0] = to_tf32(As[r0*PAD + kb + q]); \
            aa[mi][1] = to_tf32(As[(r0+8)*PAD + kb + q]); \
            aa[mi][2] = to_tf32(As[r0*PAD + kb + q + 4]); \
            aa[mi][3] = to_tf32(As[(r0+8)*PAD + kb + q + 4]); } \
        _Pragma("unroll") for (int nt = 0; nt < 8; nt++) { \
            int n = wn*64 + nt*8 + g; \
            bb[nt][0] = Bs[n*PAD + kb + q]; \
            bb[nt][1] = Bs[n*PAD + kb + q + 4]; } \
        _Pragma("unroll") for (int mi = 0; mi < 2; mi++) \
            _Pragma("unroll") for (int nt = 0; nt < 8; nt++) \
                mma_tf32(acc[mi][nt], aa[mi], bb[nt]); \
    } } while (0)

    ISSUE(0, 0);
    ISSUE(1, 1);
    for (int kc = 0; kc < NCH; kc++) {
        if (kc == NCH - 1) { CP_WAIT(0); } else { CP_WAIT(1); }
        __syncthreads();
        if (kc & 1) COMPUTE(1); else COMPUTE(0);
        __syncthreads();
        if (kc + 2 < NCH) { if (kc & 1) ISSUE(1, kc + 2); else ISSUE(0, kc + 2); }
    }

    // ---------------- epilogue ----------------
    float w0 = gw[0], w1 = gw[1], w2 = gw[2];
    float mx = fmaxf(w0, fmaxf(w1, w2));
    float e0 = __expf(w0 - mx), e1 = __expf(w1 - mx), e2 = __expf(w2 - mx);
    float inv = 1.0f / (e0 + e1 + e2);
    float A0 = e0 * inv, A1 = e1 * inv, A2 = e2 * inv;
    float k0c = 0.5f * A0 - 0.5f * A1;
    float k1c = 0.5f * A0 - 1.5f * A2;
    float k2c = 1.5f * A1;
    float k3c = 2.5f * A2;

    const float* rn_s = smemf + RN_OFF;
    const int*   lm_s = (const int*)(smemf + LM_OFF);
    const float* F_s  = smemf + F_OFF;
    float*       part = smemf + PART_OFF;   // [4][128]

#pragma unroll
    for (int mi = 0; mi < 2; mi++) {
        int r0 = wm*32 + mi*16 + g;
        int tr0 = t0 + r0, tr1 = tr0 + 8;
        float rn0 = rn_s[r0], rn1 = rn_s[r0 + 8];
        float s0 = 0.f, s1 = 0.f;
#pragma unroll
        for (int nt = 0; nt < 8; nt++) {
            int c0 = wn*64 + nt*8 + q*2;
            int l0 = lm_s[c0], l1 = lm_s[c0 + 1];
            float F0 = F_s[c0], F1 = F_s[c0 + 1];
            float* a = acc[mi][nt];
            float C, p;
            C = a[0]*rn0; p = ((k3c*C + k2c)*C + k1c)*C + k0c; a[0] = (l0 < tr0) ? p*F0 : 0.f;
            C = a[1]*rn0; p = ((k3c*C + k2c)*C + k1c)*C + k0c; a[1] = (l1 < tr0) ? p*F1 : 0.f;
            C = a[2]*rn1; p = ((k3c*C + k2c)*C + k1c)*C + k0c; a[2] = (l0 < tr1) ? p*F0 : 0.f;
            C = a[3]*rn1; p = ((k3c*C + k2c)*C + k1c)*C + k0c; a[3] = (l1 < tr1) ? p*F1 : 0.f;
            s0 += a[0] + a[1];
            s1 += a[2] + a[3];
        }
        s0 += __shfl_xor_sync(0xFFFFFFFFu, s0, 1);
        s0 += __shfl_xor_sync(0xFFFFFFFFu, s0, 2);
        s1 += __shfl_xor_sync(0xFFFFFFFFu, s1, 1);
        s1 += __shfl_xor_sync(0xFFFFFFFFu, s1, 2);
        if (q == 0) {
            part[wn*128 + r0]     = s0;
            part[wn*128 + r0 + 8] = s1;
        }
    }
    __syncthreads();

#pragma unroll
    for (int mi = 0; mi < 2; mi++) {
        int r0 = wm*32 + mi*16 + g;
        int tr0 = t0 + r0, tr1 = tr0 + 8;
        float tot0 = part[r0]   + part[128 + r0]   + part[256 + r0]   + part[384 + r0];
        float tot1 = part[r0+8] + part[128 + r0+8] + part[256 + r0+8] + part[384 + r0+8];
        float Et0 = __expf(-a_td * (float)tr0 * (1.0f / 4096.0f));
        float Et1 = __expf(-a_td * (float)tr1 * (1.0f / 4096.0f));
        float sc0 = Et0 / fmaxf(tot0 * Et0, 1e-6f);
        float sc1 = Et1 / fmaxf(tot1 * Et1, 1e-6f);
        float* o0 = out + (size_t)(bT + tr0) * (R_ + 1);
        float* o1 = out + (size_t)(bT + tr1) * (R_ + 1);
#pragma unroll
        for (int nt = 0; nt < 8; nt++) {
            int c0 = wn*64 + nt*8 + q*2;
            float* a = acc[mi][nt];
            o0[c0]     = a[0] * sc0;
            o0[c0 + 1] = a[1] * sc0;
            o1[c0]     = a[2] * sc1;
            o1[c0 + 1] = a[3] * sc1;
        }
    }
    if (tid < MT) out[(size_t)(bT + t0 + tid) * (R_ + 1) + R_] = 1.0f;
}

// ---------------------------------------------------------------------------
extern "C" void kernel_launch(void* const* d_in, const int* in_sizes, int n_in,
                              void* d_out, int out_size) {
    const float* z  = (const float*)d_in[0];
    const float* gw = (const float*)d_in[1];
    const float* ta = (const float*)d_in[2];
    float* out = (float*)d_out;

    cudaFuncSetAttribute(main_kernel, cudaFuncAttributeMaxDynamicSharedMemorySize, SMEM_BYTES);

    norm_kernel<<<(B_ * T_) / 8, 256>>>(z);
    gather_kernel<<<dim3(R_, B_), 128>>>(z);
    main_kernel<<<dim3(T_ / MT, B_), NTH, SMEM_BYTES>>>(z, gw, ta, out);
}